// round 5
// baseline (speedup 1.0000x reference)
#include <cuda_runtime.h>
#include <cstdint>

// Problem constants (stagenet_46445776339346): V=5, B=2, C=32, H=W=128, D=32, G=8
#define NV 5
#define NB 2
#define NC 32
#define NH 128
#define NW 128
#define ND 32
#define NG 8
#define HW (NH * NW)

// ---------------------------------------------------------------------------
// Device scratch (no runtime allocation allowed)
// ---------------------------------------------------------------------------
__device__ float  g_rot[NB][NV][9];
__device__ float  g_trans[NB][NV][3];
// features transposed to [V, B, H*W, C]: one bilinear tap = 128 contiguous bytes.
__device__ float4 g_featT[(size_t)NV * NB * HW * (NC / 4)];

// ---------------------------------------------------------------------------
// fp32 4x4 inverse: sgetf2-style LU (reciprocal scal) + lu_solve(identity)
// with OpenBLAS-style trsm: unit-lower forward sub, then upper back sub using
// PRE-INVERTED diagonal (reciprocal multiply, not division).
// ---------------------------------------------------------------------------
__device__ void inv4_lapack_f32(const float* A_rm /*row-major 16*/, float* Ai_rm) {
    float a[16];   // column-major: a[c*4+r]
    int   piv[4];
#pragma unroll
    for (int r = 0; r < 4; r++)
#pragma unroll
        for (int c = 0; c < 4; c++) a[c * 4 + r] = A_rm[r * 4 + c];

    // sgetf2: LU with partial pivoting (bit-identical to sgetrf2 at 4x4)
#pragma unroll
    for (int j = 0; j < 4; j++) {
        int jp = j; float amax = fabsf(a[j * 4 + j]);
        for (int i = j + 1; i < 4; i++) {
            float v = fabsf(a[j * 4 + i]);
            if (v > amax) { amax = v; jp = i; }   // isamax: first max kept
        }
        piv[j] = jp;
        if (jp != j)
#pragma unroll
            for (int c = 0; c < 4; c++) {
                float t = a[c * 4 + j]; a[c * 4 + j] = a[c * 4 + jp]; a[c * 4 + jp] = t;
            }
        float ainv = __fdiv_rn(1.0f, a[j * 4 + j]);
        for (int i = j + 1; i < 4; i++)
            a[j * 4 + i] = __fmul_rn(a[j * 4 + i], ainv);
        for (int k = j + 1; k < 4; k++) {
            float temp = -a[k * 4 + j];
            for (int i = j + 1; i < 4; i++)
                a[k * 4 + i] = fmaf(a[j * 4 + i], temp, a[k * 4 + i]);
        }
    }

    // OpenBLAS trsm packs the triangular factor with inverted diagonal:
    float dinv[4];
#pragma unroll
    for (int k = 0; k < 4; k++) dinv[k] = __fdiv_rn(1.0f, a[k * 4 + k]);

    // solve A X = I: permute RHS, unit-lower forward, upper back substitution
#pragma unroll
    for (int c = 0; c < 4; c++) {
        float b[4] = {0.f, 0.f, 0.f, 0.f};
        b[c] = 1.0f;
#pragma unroll
        for (int j = 0; j < 4; j++) { float t = b[j]; b[j] = b[piv[j]]; b[piv[j]] = t; }
        // unit-lower forward substitution
#pragma unroll
        for (int k = 0; k < 4; k++) {
            float bk = b[k];
            if (bk != 0.f)
                for (int i = k + 1; i < 4; i++)
                    b[i] = fmaf(-bk, a[k * 4 + i], b[i]);
        }
        // upper back substitution, reciprocal-multiply diagonal (OpenBLAS)
#pragma unroll
        for (int k = 3; k >= 0; k--) {
            b[k] = __fmul_rn(b[k], dinv[k]);
            float bk = b[k];
            for (int i = 0; i < k; i++)
                b[i] = fmaf(-bk, a[k * 4 + i], b[i]);
        }
#pragma unroll
        for (int r = 0; r < 4; r++) Ai_rm[r * 4 + c] = b[r];
    }
}

// Build combined 4x4 (fp32): rows 0..2 = K[:3,:3] @ ext[:3,:4], row 3 = ext row 3.
// fma-chain contraction (best-performing config from R3).
__device__ void make_comb_f32(const float* pm, int b, int v, float* M /*16 rm*/) {
    const float* ext = pm + ((size_t)(b * NV + v) * 2 + 0) * 16;
    const float* K   = pm + ((size_t)(b * NV + v) * 2 + 1) * 16;
#pragma unroll
    for (int r = 0; r < 3; r++)
#pragma unroll
        for (int c = 0; c < 4; c++) {
            float s = __fmul_rn(K[r * 4 + 0], ext[0 * 4 + c]);
            s = fmaf(K[r * 4 + 1], ext[1 * 4 + c], s);
            s = fmaf(K[r * 4 + 2], ext[2 * 4 + c], s);
            M[r * 4 + c] = s;
        }
#pragma unroll
    for (int c = 0; c < 4; c++) M[12 + c] = ext[12 + c];
}

__global__ void setup_kernel(const float* __restrict__ pm) {
    if (threadIdx.x != 0) return;
    for (int b = 0; b < NB; b++) {
        float Mr[16], Mi[16];
        make_comb_f32(pm, b, 0, Mr);
        inv4_lapack_f32(Mr, Mi);
        for (int v = 1; v < NV; v++) {
            float Ms[16];
            make_comb_f32(pm, b, v, Ms);
            for (int r = 0; r < 3; r++) {
                for (int c = 0; c < 4; c++) {
                    float s = __fmul_rn(Ms[r * 4 + 0], Mi[0 * 4 + c]);
                    s = fmaf(Ms[r * 4 + 1], Mi[1 * 4 + c], s);
                    s = fmaf(Ms[r * 4 + 2], Mi[2 * 4 + c], s);
                    s = fmaf(Ms[r * 4 + 3], Mi[3 * 4 + c], s);
                    if (c < 3) g_rot[b][v][r * 3 + c] = s;
                    else       g_trans[b][v][r] = s;
                }
            }
        }
    }
}

// ---------------------------------------------------------------------------
// Transpose features [V*B, C, HW] -> [V*B, HW, C]
// ---------------------------------------------------------------------------
__global__ void transpose_kernel(const float* __restrict__ fea) {
    __shared__ float tile[32][33];
    int vb = blockIdx.y;
    int pb = blockIdx.x * 32;
    int tx = threadIdx.x, ty = threadIdx.y;
    tile[ty][tx] = fea[(size_t)vb * NC * HW + (size_t)ty * HW + pb + tx];
    __syncthreads();
    ((float*)g_featT)[((size_t)vb * HW + pb + ty) * NC + tx] = tile[tx][ty];
}

// ---------------------------------------------------------------------------
// Sequential (lane-order, ascending) sum across the warp — matches a
// strided-axis loop reduce. All lanes get the result.
// ---------------------------------------------------------------------------
__device__ __forceinline__ float warp_seq_sum(float x) {
    const unsigned FULL = 0xffffffffu;
    float s = 0.f;
#pragma unroll
    for (int k = 0; k < 32; k++)
        s = __fadd_rn(s, __shfl_sync(FULL, x, k));
    return s;
}

// ---------------------------------------------------------------------------
// Main kernel: one warp per ref pixel, lane = depth hypothesis.
// ---------------------------------------------------------------------------
__global__ void __launch_bounds__(256) stagenet_main(
    const float* __restrict__ depth_hypo,
    const float* __restrict__ reg_w,
    float* __restrict__ out) {
    const unsigned FULL = 0xffffffffu;
    int warp = blockIdx.x * (blockDim.x >> 5) + (threadIdx.x >> 5);
    int lane = threadIdx.x & 31;

    int b  = warp >> 14;
    int hw = warp & (HW - 1);
    int h  = hw >> 7;
    int w  = hw & (NW - 1);

    const float4* refp = g_featT + ((size_t)b * HW + hw) * 8;   // view 0
    float4 rf[8];
#pragma unroll
    for (int j = 0; j < 8; j++) rf[j] = __ldg(refp + j);

    float dep = depth_hypo[((size_t)(b * ND + lane)) * HW + hw];
    float xw = (float)w, yh = (float)h;

    float acc[8];
#pragma unroll
    for (int j = 0; j < 8; j++) acc[j] = 0.f;
    float cw_sum = 1e-8f;
    bool first = true;

#pragma unroll
    for (int v = 1; v < NV; v++) {
        const float* R = g_rot[b][v];
        const float* T = g_trans[b][v];
        // rot @ [x, y, 1]: gemm-path fma chain, ascending k
        float rx = fmaf(R[2], 1.f, fmaf(R[1], yh, __fmul_rn(R[0], xw)));
        float ry = fmaf(R[5], 1.f, fmaf(R[4], yh, __fmul_rn(R[3], xw)));
        float rz = fmaf(R[8], 1.f, fmaf(R[7], yh, __fmul_rn(R[6], xw)));
        // proj_xyz = rot_xyz * depth + trans (elementwise: separate mul/add)
        float X = __fadd_rn(__fmul_rn(rx, dep), T[0]);
        float Y = __fadd_rn(__fmul_rn(ry, dep), T[1]);
        float Z = __fadd_rn(__fmul_rn(rz, dep), T[2]);
        if (Z == 0.f) Z = 1e-9f;
        float px = __fdiv_rn(X, Z);
        float py = __fdiv_rn(Y, Z);

        float x0f = floorf(px), y0f = floorf(py);
        int   x0 = (int)x0f,   y0 = (int)y0f;
        float wx1 = __fsub_rn(px, x0f), wx0 = __fsub_rn(1.f, wx1);
        float wy1 = __fsub_rn(py, y0f), wy0 = __fsub_rn(1.f, wy1);

        // tap order matches reference: (x0,y0),(x1,y0),(x0,y1),(x1,y1)
        int   xs[4]  = {x0, x0 + 1, x0, x0 + 1};
        int   ys[4]  = {y0, y0, y0 + 1, y0 + 1};
        float wts[4] = {__fmul_rn(wx0, wy0), __fmul_rn(wx1, wy0),
                        __fmul_rn(wx0, wy1), __fmul_rn(wx1, wy1)};
        bool  ok[4];
        const float4* tp[4];
        const float4* base = g_featT + ((size_t)(v * NB + b) * HW) * 8;
#pragma unroll
        for (int t = 0; t < 4; t++) {
            ok[t] = (xs[t] >= 0) && (xs[t] < NW) && (ys[t] >= 0) && (ys[t] < NH);
            tp[t] = base + (size_t)(ys[t] * NW + xs[t]) * 8;
        }

        float cf[8];
        float s = 0.f;
#pragma unroll
        for (int g = 0; g < 8; g++) {
            // warped per channel: taps summed in reference order (mul+add)
            float wc0 = 0.f, wc1 = 0.f, wc2 = 0.f, wc3 = 0.f;
#pragma unroll
            for (int t = 0; t < 4; t++) {
                if (ok[t]) {
                    float4 q = __ldg(tp[t] + g);
                    wc0 = __fadd_rn(wc0, __fmul_rn(q.x, wts[t]));
                    wc1 = __fadd_rn(wc1, __fmul_rn(q.y, wts[t]));
                    wc2 = __fadd_rn(wc2, __fmul_rn(q.z, wts[t]));
                    wc3 = __fadd_rn(wc3, __fmul_rn(q.w, wts[t]));
                }
            }
            // (warped * ref).mean over 4 channels: elementwise mul, seq sum, /4
            float p = __fmul_rn(wc0, rf[g].x);
            p = __fadd_rn(p, __fmul_rn(wc1, rf[g].y));
            p = __fadd_rn(p, __fmul_rn(wc2, rf[g].z));
            p = __fadd_rn(p, __fmul_rn(wc3, rf[g].w));
            cf[g] = __fdiv_rn(p, 4.0f);
            s = (g == 0) ? cf[0] : __fadd_rn(s, cf[g]);
        }

        // softmax over depth (strided axis -> sequential loop reduce)
        float m = s;
#pragma unroll
        for (int o = 16; o; o >>= 1) m = fmaxf(m, __shfl_xor_sync(FULL, m, o));
        float e = expf(__fsub_rn(s, m));
        float es = warp_seq_sum(e);
        float wv = __fmul_rn(__fdiv_rn(e, es), 0.17677669529663687f);  // 1/sqrt(32)

        cw_sum = __fadd_rn(cw_sum, wv);
#pragma unroll
        for (int g = 0; g < 8; g++) {
            float t = __fmul_rn(wv, cf[g]);
            acc[g] = first ? t : __fadd_rn(acc[g], t);
        }
        first = false;
    }

    // cor_feats / cor_weight_sum, then reg_w contraction (fma chain)
    float logit = 0.f;
#pragma unroll
    for (int g = 0; g < 8; g++) {
        float vgl = __fdiv_rn(acc[g], cw_sum);
        float rw  = __ldg(reg_w + g);
        logit = (g == 0) ? __fmul_rn(rw, vgl) : fmaf(rw, vgl, logit);
    }

    // final softmax over depth (sequential sum)
    float m2 = logit;
#pragma unroll
    for (int o = 16; o; o >>= 1) m2 = fmaxf(m2, __shfl_xor_sync(FULL, m2, o));
    float e2 = expf(__fsub_rn(logit, m2));
    float es2 = warp_seq_sum(e2);
    float attn = __fdiv_rn(e2, es2);

    // outputs: [depth (B*H*W)] then [attn (B*D*H*W)]
    out[(size_t)NB * HW + ((size_t)(b * ND + lane)) * HW + hw] = attn;

    float amax = attn;
#pragma unroll
    for (int o = 16; o; o >>= 1) amax = fmaxf(amax, __shfl_xor_sync(FULL, amax, o));
    unsigned msk = __ballot_sync(FULL, attn == amax);
    int idx = __ffs(msk) - 1;   // first max, matching jnp.argmax
    if (lane == idx) out[(size_t)b * HW + hw] = dep;
}

// ---------------------------------------------------------------------------
// Launch
// ---------------------------------------------------------------------------
extern "C" void kernel_launch(void* const* d_in, const int* in_sizes, int n_in,
                              void* d_out, int out_size) {
    const float* features   = (const float*)d_in[0];
    const float* proj       = (const float*)d_in[1];
    const float* depth_hypo = (const float*)d_in[2];
    const float* reg_w      = (const float*)d_in[3];
    float* out = (float*)d_out;

    setup_kernel<<<1, 32>>>(proj);
    transpose_kernel<<<dim3(HW / 32, NV * NB), dim3(32, 32)>>>(features);
    stagenet_main<<<(NB * HW) / 8, 256>>>(depth_hypo, reg_w, out);
}